// round 1
// baseline (speedup 1.0000x reference)
#include <cuda_runtime.h>
#include <math.h>

#define Bv  2
#define Nv  2048
#define Dv  1024
#define Hv  16
#define DHv 64
#define Mv  (Bv*Nv)

// Scratch (device globals: allocation-free contract)
__device__ float g_Q[(size_t)Mv * Dv];
__device__ float g_K[(size_t)Mv * Dv];
__device__ float g_V[(size_t)Mv * Dv];
__device__ float g_A[(size_t)Mv * Dv];

// ---------------------------------------------------------------------------
// Y[m,n] = sum_k X[m,k] * W[n,k] + bias[n]   (X:[M,K] row-major, W:[N,K] row-major)
// 64x64 tile, TK=16, 256 threads, 4x4 per-thread microkernel.
// ---------------------------------------------------------------------------
__global__ __launch_bounds__(256) void gemm_bias_kernel(
    const float* __restrict__ X, const float* __restrict__ W,
    const float* __restrict__ bias, float* __restrict__ Y,
    int Msz, int Nsz, int Ksz)
{
    __shared__ float As[16][64];
    __shared__ float Bs[16][64];

    const int t  = threadIdx.x;
    const int tx = t & 15;
    const int ty = t >> 4;
    const int m0 = blockIdx.y * 64;
    const int n0 = blockIdx.x * 64;
    const int lr = t >> 2;          // 0..63
    const int lc = (t & 3) << 2;    // 0,4,8,12

    const float* Xp = X + (size_t)(m0 + lr) * Ksz + lc;
    const float* Wp = W + (size_t)(n0 + lr) * Ksz + lc;

    float acc[4][4];
#pragma unroll
    for (int i = 0; i < 4; i++)
#pragma unroll
        for (int j = 0; j < 4; j++) acc[i][j] = 0.0f;

    for (int k0 = 0; k0 < Ksz; k0 += 16) {
        float4 xa = *(const float4*)(Xp + k0);
        float4 xb = *(const float4*)(Wp + k0);
        As[lc + 0][lr] = xa.x; As[lc + 1][lr] = xa.y;
        As[lc + 2][lr] = xa.z; As[lc + 3][lr] = xa.w;
        Bs[lc + 0][lr] = xb.x; Bs[lc + 1][lr] = xb.y;
        Bs[lc + 2][lr] = xb.z; Bs[lc + 3][lr] = xb.w;
        __syncthreads();
#pragma unroll
        for (int kk = 0; kk < 16; kk++) {
            float4 av = *(const float4*)&As[kk][ty << 2];
            float4 bv = *(const float4*)&Bs[kk][tx << 2];
            acc[0][0] += av.x * bv.x; acc[0][1] += av.x * bv.y;
            acc[0][2] += av.x * bv.z; acc[0][3] += av.x * bv.w;
            acc[1][0] += av.y * bv.x; acc[1][1] += av.y * bv.y;
            acc[1][2] += av.y * bv.z; acc[1][3] += av.y * bv.w;
            acc[2][0] += av.z * bv.x; acc[2][1] += av.z * bv.y;
            acc[2][2] += av.z * bv.z; acc[2][3] += av.z * bv.w;
            acc[3][0] += av.w * bv.x; acc[3][1] += av.w * bv.y;
            acc[3][2] += av.w * bv.z; acc[3][3] += av.w * bv.w;
        }
        __syncthreads();
    }

    float4 bb = *(const float4*)&bias[n0 + (tx << 2)];
#pragma unroll
    for (int i = 0; i < 4; i++) {
        float4 o;
        o.x = acc[i][0] + bb.x;
        o.y = acc[i][1] + bb.y;
        o.z = acc[i][2] + bb.z;
        o.w = acc[i][3] + bb.w;
        *(float4*)&Y[(size_t)(m0 + (ty << 2) + i) * Nsz + n0 + (tx << 2)] = o;
    }
}

// ---------------------------------------------------------------------------
// Flash attention per (batch, head): 64 query rows / CTA, KV tiles of 64,
// online softmax (no 1/sqrt(dh) scaling, faithful to reference).
// 256 threads, 4x4 per-thread S microkernel, P staged through smem for P*V.
// ---------------------------------------------------------------------------
#define ATTN_SMEM ((64*64 + 64*65 + 64*64 + 64*65) * 4)

__global__ __launch_bounds__(256) void attn_kernel(
    const float* __restrict__ Qp, const float* __restrict__ Kp,
    const float* __restrict__ Vp, float* __restrict__ Op)
{
    extern __shared__ float sm[];
    float* Qs = sm;               // [64][64]
    float* Ks = Qs + 64 * 64;     // [64][65] padded
    float* Vs = Ks + 64 * 65;     // [64][64]
    float* Ps = Vs + 64 * 64;     // [64][65] padded

    const int t  = threadIdx.x;
    const int tx = t & 15;
    const int ty = t >> 4;
    const int q0 = blockIdx.x * 64;
    const int h  = blockIdx.y;
    const int b  = blockIdx.z;
    const size_t base = (size_t)b * Nv * Dv + (size_t)h * DHv;

    // Load Q tile [64 rows x 64 dh]
#pragma unroll
    for (int i = 0; i < 4; i++) {
        int idx = t + i * 256;
        int r = idx >> 4;
        int c = (idx & 15) << 2;
        float4 v = *(const float4*)&Qp[base + (size_t)(q0 + r) * Dv + c];
        *(float4*)&Qs[r * 64 + c] = v;
    }

    float m_i[4], l_i[4], acc[4][4];
#pragma unroll
    for (int i = 0; i < 4; i++) {
        m_i[i] = -1e30f;
        l_i[i] = 0.0f;
#pragma unroll
        for (int j = 0; j < 4; j++) acc[i][j] = 0.0f;
    }

    for (int kt = 0; kt < Nv / 64; kt++) {
        __syncthreads();   // prior tile's Ks/Vs/Ps reads complete
        // Load K and V tiles
#pragma unroll
        for (int i = 0; i < 4; i++) {
            int idx = t + i * 256;
            int r = idx >> 4;
            int c = (idx & 15) << 2;
            size_t g = base + (size_t)(kt * 64 + r) * Dv + c;
            float4 kv = *(const float4*)&Kp[g];
            Ks[r * 65 + c + 0] = kv.x; Ks[r * 65 + c + 1] = kv.y;
            Ks[r * 65 + c + 2] = kv.z; Ks[r * 65 + c + 3] = kv.w;
            float4 vv = *(const float4*)&Vp[g];
            *(float4*)&Vs[r * 64 + c] = vv;
        }
        __syncthreads();

        // S = Q * K^T   (4x4 per thread)
        float s[4][4];
#pragma unroll
        for (int i = 0; i < 4; i++)
#pragma unroll
            for (int j = 0; j < 4; j++) s[i][j] = 0.0f;

#pragma unroll 8
        for (int kk = 0; kk < 64; kk++) {
            float a0 = Qs[((ty << 2) + 0) * 64 + kk];
            float a1 = Qs[((ty << 2) + 1) * 64 + kk];
            float a2 = Qs[((ty << 2) + 2) * 64 + kk];
            float a3 = Qs[((ty << 2) + 3) * 64 + kk];
            float b0 = Ks[((tx << 2) + 0) * 65 + kk];
            float b1 = Ks[((tx << 2) + 1) * 65 + kk];
            float b2 = Ks[((tx << 2) + 2) * 65 + kk];
            float b3 = Ks[((tx << 2) + 3) * 65 + kk];
            s[0][0] += a0 * b0; s[0][1] += a0 * b1; s[0][2] += a0 * b2; s[0][3] += a0 * b3;
            s[1][0] += a1 * b0; s[1][1] += a1 * b1; s[1][2] += a1 * b2; s[1][3] += a1 * b3;
            s[2][0] += a2 * b0; s[2][1] += a2 * b1; s[2][2] += a2 * b2; s[2][3] += a2 * b3;
            s[3][0] += a3 * b0; s[3][1] += a3 * b1; s[3][2] += a3 * b2; s[3][3] += a3 * b3;
        }

        // Online softmax update per row (row shared by 16 threads: shfl 1..8)
#pragma unroll
        for (int i = 0; i < 4; i++) {
            float tm = fmaxf(fmaxf(s[i][0], s[i][1]), fmaxf(s[i][2], s[i][3]));
#pragma unroll
            for (int o = 8; o > 0; o >>= 1)
                tm = fmaxf(tm, __shfl_xor_sync(0xffffffffu, tm, o));
            float nm = fmaxf(m_i[i], tm);
            float sc = __expf(m_i[i] - nm);
            float rs = 0.0f;
#pragma unroll
            for (int j = 0; j < 4; j++) {
                float p = __expf(s[i][j] - nm);
                s[i][j] = p;
                rs += p;
            }
#pragma unroll
            for (int o = 8; o > 0; o >>= 1)
                rs += __shfl_xor_sync(0xffffffffu, rs, o);
            l_i[i] = l_i[i] * sc + rs;
            m_i[i] = nm;
#pragma unroll
            for (int j = 0; j < 4; j++) acc[i][j] *= sc;
            // stage P into smem
#pragma unroll
            for (int j = 0; j < 4; j++)
                Ps[((ty << 2) + i) * 65 + (tx << 2) + j] = s[i][j];
        }
        __syncthreads();

        // O += P * V
#pragma unroll 4
        for (int j = 0; j < 64; j++) {
            float4 vv = *(const float4*)&Vs[j * 64 + (tx << 2)];
            float p0 = Ps[((ty << 2) + 0) * 65 + j];
            float p1 = Ps[((ty << 2) + 1) * 65 + j];
            float p2 = Ps[((ty << 2) + 2) * 65 + j];
            float p3 = Ps[((ty << 2) + 3) * 65 + j];
            acc[0][0] += p0 * vv.x; acc[0][1] += p0 * vv.y; acc[0][2] += p0 * vv.z; acc[0][3] += p0 * vv.w;
            acc[1][0] += p1 * vv.x; acc[1][1] += p1 * vv.y; acc[1][2] += p1 * vv.z; acc[1][3] += p1 * vv.w;
            acc[2][0] += p2 * vv.x; acc[2][1] += p2 * vv.y; acc[2][2] += p2 * vv.z; acc[2][3] += p2 * vv.w;
            acc[3][0] += p3 * vv.x; acc[3][1] += p3 * vv.y; acc[3][2] += p3 * vv.z; acc[3][3] += p3 * vv.w;
        }
    }

    // Epilogue: normalize and write (heads already interleaved at col h*64)
#pragma unroll
    for (int i = 0; i < 4; i++) {
        float inv = 1.0f / l_i[i];
        float4 o;
        o.x = acc[i][0] * inv;
        o.y = acc[i][1] * inv;
        o.z = acc[i][2] * inv;
        o.w = acc[i][3] * inv;
        *(float4*)&Op[base + (size_t)(q0 + (ty << 2) + i) * Dv + (tx << 2)] = o;
    }
}

// ---------------------------------------------------------------------------
extern "C" void kernel_launch(void* const* d_in, const int* in_sizes, int n_in,
                              void* d_out, int out_size)
{
    const float* q  = (const float*)d_in[0];
    const float* k  = (const float*)d_in[1];
    const float* v  = (const float*)d_in[2];
    const float* Wq = (const float*)d_in[3];
    const float* bq = (const float*)d_in[4];
    const float* Wk = (const float*)d_in[5];
    const float* bk = (const float*)d_in[6];
    const float* Wv = (const float*)d_in[7];
    const float* bv = (const float*)d_in[8];
    const float* Wo = (const float*)d_in[9];
    const float* bo = (const float*)d_in[10];
    float* out = (float*)d_out;

    float *gQ, *gK, *gV, *gA;
    cudaGetSymbolAddress((void**)&gQ, g_Q);
    cudaGetSymbolAddress((void**)&gK, g_K);
    cudaGetSymbolAddress((void**)&gV, g_V);
    cudaGetSymbolAddress((void**)&gA, g_A);

    cudaFuncSetAttribute(attn_kernel,
                         cudaFuncAttributeMaxDynamicSharedMemorySize, ATTN_SMEM);

    dim3 gg(Dv / 64, Mv / 64);  // (16, 64)
    gemm_bias_kernel<<<gg, 256>>>(q, Wq, bq, gQ, Mv, Dv, Dv);
    gemm_bias_kernel<<<gg, 256>>>(k, Wk, bk, gK, Mv, Dv, Dv);
    gemm_bias_kernel<<<gg, 256>>>(v, Wv, bv, gV, Mv, Dv, Dv);

    attn_kernel<<<dim3(Nv / 64, Hv, Bv), 256, ATTN_SMEM>>>(gQ, gK, gV, gA);

    gemm_bias_kernel<<<gg, 256>>>(gA, Wo, bo, out, Mv, Dv, Dv);
}

// round 3
// speedup vs baseline: 1.4142x; 1.4142x over previous
#include <cuda_runtime.h>
#include <math.h>
#include <stdint.h>

#define Bv  2
#define Nv  2048
#define Dv  1024
#define Hv  16
#define DHv 64
#define Mv  (Bv*Nv)

// Scratch (device globals: allocation-free contract)
__device__ float g_Q[(size_t)Mv * Dv];
__device__ float g_K[(size_t)Mv * Dv];
__device__ float g_V[(size_t)Mv * Dv];
__device__ float g_A[(size_t)Mv * Dv];

// ---------------------------------------------------------------------------
// helpers
// ---------------------------------------------------------------------------
__device__ __forceinline__ uint32_t f2tf(float f) {
    uint32_t r;
    asm("cvt.rna.tf32.f32 %0, %1;" : "=r"(r) : "f"(f));
    return r;
}
// split x into hi (tf32) and lo (tf32 of residual)
__device__ __forceinline__ void tfsplit(float x, uint32_t& hi, uint32_t& lo) {
    hi = f2tf(x);
    lo = f2tf(x - __uint_as_float(hi));
}

#define MMA_TF32(d, a0, a1, a2, a3, b0, b1)                                   \
    asm volatile(                                                             \
        "mma.sync.aligned.m16n8k8.row.col.f32.tf32.tf32.f32 "                 \
        "{%0,%1,%2,%3},{%4,%5,%6,%7},{%8,%9},{%0,%1,%2,%3};"                  \
        : "+f"(d[0]), "+f"(d[1]), "+f"(d[2]), "+f"(d[3])                      \
        : "r"(a0), "r"(a1), "r"(a2), "r"(a3), "r"(b0), "r"(b1))

// split-tf32 product: hi*hi + hi*lo + lo*hi
#define MMA3(d, ah, al, bh, bl)                                               \
    MMA_TF32(d, ah[0], ah[1], ah[2], ah[3], bh[0], bh[1]);                    \
    MMA_TF32(d, ah[0], ah[1], ah[2], ah[3], bl[0], bl[1]);                    \
    MMA_TF32(d, al[0], al[1], al[2], al[3], bh[0], bh[1]);

__device__ __forceinline__ void cp_async16(uint32_t daddr, const void* src) {
    asm volatile("cp.async.cg.shared.global [%0], [%1], 16;"
                 :: "r"(daddr), "l"(src));
}

// ---------------------------------------------------------------------------
// Y[m,n] = sum_k X[m,k]*W[n,k] + bias[n],  M=4096, N=K=1024 fixed.
// CTA 128x128, Kc=32, split-tf32 mma.sync (3 MMAs/pair), cp.async dbl buffer.
// ---------------------------------------------------------------------------
#define GSTRIDE 36
#define GTILE   (128 * GSTRIDE)
#define GSMEM   (4 * GTILE * 4)

__global__ __launch_bounds__(256) void gemm_tc(
    const float* __restrict__ X, const float* __restrict__ W,
    const float* __restrict__ bias, float* __restrict__ Y)
{
    extern __shared__ float sm[];
    float* As = sm;              // [2][128][36]
    float* Bs = sm + 2 * GTILE;  // [2][128][36]

    const int t    = threadIdx.x;
    const int lane = t & 31;
    const int warp = t >> 5;
    const int gid  = lane >> 2;
    const int tq   = lane & 3;
    const int wm   = warp >> 2;   // 0..1
    const int wn   = warp & 3;    // 0..3
    const int m0   = blockIdx.y * 128;
    const int n0   = blockIdx.x * 128;

    const uint32_t sbase = (uint32_t)__cvta_generic_to_shared(sm);

    float acc[4][4][4];
#pragma unroll
    for (int mf = 0; mf < 4; mf++)
#pragma unroll
        for (int nf = 0; nf < 4; nf++)
#pragma unroll
            for (int c = 0; c < 4; c++) acc[mf][nf][c] = 0.0f;

#define GEMM_ISSUE(buf, k0)                                                    \
    {                                                                          \
        _Pragma("unroll")                                                      \
        for (int i = 0; i < 4; i++) {                                          \
            int idx = t + i * 256;                                             \
            int row = idx >> 3;                                                \
            int c4  = idx & 7;                                                 \
            cp_async16(sbase + ((buf) * GTILE + row * GSTRIDE + c4 * 4) * 4,   \
                       X + (size_t)(m0 + row) * Dv + (k0) + c4 * 4);           \
            cp_async16(sbase + ((2 * GTILE) + (buf) * GTILE + row * GSTRIDE +  \
                                c4 * 4) * 4,                                   \
                       W + (size_t)(n0 + row) * Dv + (k0) + c4 * 4);           \
        }                                                                      \
        asm volatile("cp.async.commit_group;");                                \
    }

    GEMM_ISSUE(0, 0);

    for (int it = 0; it < 32; it++) {
        asm volatile("cp.async.wait_group 0;" ::: "memory");
        __syncthreads();
        if (it + 1 < 32) GEMM_ISSUE((it + 1) & 1, (it + 1) * 32);

        const float* A = As + (it & 1) * GTILE;
        const float* B = Bs + (it & 1) * GTILE;

#pragma unroll
        for (int ks = 0; ks < 4; ks++) {
            uint32_t ah[4][4], al[4][4];
            const int c = ks * 8 + tq;
#pragma unroll
            for (int mf = 0; mf < 4; mf++) {
                int r = wm * 64 + mf * 16 + gid;
                tfsplit(A[r * GSTRIDE + c],       ah[mf][0], al[mf][0]);
                tfsplit(A[(r + 8) * GSTRIDE + c], ah[mf][1], al[mf][1]);
                tfsplit(A[r * GSTRIDE + c + 4],   ah[mf][2], al[mf][2]);
                tfsplit(A[(r + 8) * GSTRIDE + c + 4], ah[mf][3], al[mf][3]);
            }
#pragma unroll
            for (int nf = 0; nf < 4; nf++) {
                int n = wn * 32 + nf * 8 + gid;
                uint32_t bh[2], bl[2];
                tfsplit(B[n * GSTRIDE + c],     bh[0], bl[0]);
                tfsplit(B[n * GSTRIDE + c + 4], bh[1], bl[1]);
#pragma unroll
                for (int mf = 0; mf < 4; mf++) {
                    MMA3(acc[mf][nf], ah[mf], al[mf], bh, bl);
                }
            }
        }
    }

    // epilogue: bias + store
#pragma unroll
    for (int nf = 0; nf < 4; nf++) {
        int col = n0 + wn * 32 + nf * 8 + tq * 2;
        float2 bb = *(const float2*)&bias[col];
#pragma unroll
        for (int mf = 0; mf < 4; mf++) {
            int r = m0 + wm * 64 + mf * 16 + gid;
            float2 o;
            o.x = acc[mf][nf][0] + bb.x;
            o.y = acc[mf][nf][1] + bb.y;
            *(float2*)&Y[(size_t)r * Dv + col] = o;
            o.x = acc[mf][nf][2] + bb.x;
            o.y = acc[mf][nf][3] + bb.y;
            *(float2*)&Y[(size_t)(r + 8) * Dv + col] = o;
        }
    }
}

// ---------------------------------------------------------------------------
// Flash attention, split-tf32 mma.sync. CTA: 64 q-rows, 8 warps (4wm x 2wn),
// warp tile 16x32. Q fp32 in regs, split per use. K/V/P fp32 in smem.
// ---------------------------------------------------------------------------
#define ASTRIDE 68
#define ATILE   (64 * ASTRIDE)
#define ASMEM   ((3 * ATILE + 64 + 64 + 128 + 128) * 4)

__global__ __launch_bounds__(256) void attn_tc(
    const float* __restrict__ Qp, const float* __restrict__ Kp,
    const float* __restrict__ Vp, float* __restrict__ Op)
{
    extern __shared__ float sm[];
    float* Ks     = sm;                // [64][68]
    float* Vs     = Ks + ATILE;        // [64][68]
    float* Ps     = Vs + ATILE;        // [64][68]  (also Q staging)
    float* mstate = Ps + ATILE;        // [64]
    float* lstate = mstate + 64;       // [64]
    float* pmax   = lstate + 64;       // [2][64]
    float* psum   = pmax + 128;        // [2][64]

    const int t    = threadIdx.x;
    const int lane = t & 31;
    const int warp = t >> 5;
    const int gid  = lane >> 2;
    const int tq   = lane & 3;
    const int wm   = warp >> 1;   // 0..3
    const int wn   = warp & 1;    // 0..1
    const int q0   = blockIdx.x * 64;
    const size_t base =
        (size_t)blockIdx.z * Nv * Dv + (size_t)blockIdx.y * DHv;

    // stage Q tile (raw fp32), init softmax state
#pragma unroll
    for (int i = 0; i < 4; i++) {
        int idx = t + i * 256;
        int r   = idx >> 4;
        int c4  = (idx & 15) << 2;
        float4 v = *(const float4*)&Qp[base + (size_t)(q0 + r) * Dv + c4];
        *(float4*)&Ps[r * ASTRIDE + c4] = v;
    }
    if (t < 64) { mstate[t] = -1e30f; lstate[t] = 0.0f; }
    __syncthreads();

    // Q fragments -> registers (fp32, split per use)
    float qf[8][4];
    {
        const int r = wm * 16 + gid;
#pragma unroll
        for (int ks = 0; ks < 8; ks++) {
            int c = ks * 8 + tq;
            qf[ks][0] = Ps[r * ASTRIDE + c];
            qf[ks][1] = Ps[(r + 8) * ASTRIDE + c];
            qf[ks][2] = Ps[r * ASTRIDE + c + 4];
            qf[ks][3] = Ps[(r + 8) * ASTRIDE + c + 4];
        }
    }

    float o[4][4];
#pragma unroll
    for (int nf = 0; nf < 4; nf++)
#pragma unroll
        for (int c = 0; c < 4; c++) o[nf][c] = 0.0f;

    const int r_lo = wm * 16 + gid;
    const int r_hi = r_lo + 8;

    for (int kt = 0; kt < Nv / 64; kt++) {
        __syncthreads();
        // load K,V tiles (raw fp32)
#pragma unroll
        for (int i = 0; i < 4; i++) {
            int idx = t + i * 256;
            int r   = idx >> 4;
            int c4  = (idx & 15) << 2;
            size_t g = base + (size_t)(kt * 64 + r) * Dv + c4;
            float4 kv = *(const float4*)&Kp[g];
            *(float4*)&Ks[r * ASTRIDE + c4] = kv;
            float4 vv = *(const float4*)&Vp[g];
            *(float4*)&Vs[r * ASTRIDE + c4] = vv;
        }
        __syncthreads();

        // S = Q K^T  (split-tf32)
        float s[4][4];
#pragma unroll
        for (int nf = 0; nf < 4; nf++)
#pragma unroll
            for (int c = 0; c < 4; c++) s[nf][c] = 0.0f;
#pragma unroll
        for (int ks = 0; ks < 8; ks++) {
            const int c = ks * 8 + tq;
            uint32_t qh[4], ql[4];
#pragma unroll
            for (int e = 0; e < 4; e++) tfsplit(qf[ks][e], qh[e], ql[e]);
#pragma unroll
            for (int nf = 0; nf < 4; nf++) {
                int n = wn * 32 + nf * 8 + gid;
                uint32_t bh[2], bl[2];
                tfsplit(Ks[n * ASTRIDE + c],     bh[0], bl[0]);
                tfsplit(Ks[n * ASTRIDE + c + 4], bh[1], bl[1]);
                MMA3(s[nf], qh, ql, bh, bl);
            }
        }

        // phase A: per-row max (this warp's 32 cols)
        float mx_lo = -1e30f, mx_hi = -1e30f;
#pragma unroll
        for (int nf = 0; nf < 4; nf++) {
            mx_lo = fmaxf(mx_lo, fmaxf(s[nf][0], s[nf][1]));
            mx_hi = fmaxf(mx_hi, fmaxf(s[nf][2], s[nf][3]));
        }
        mx_lo = fmaxf(mx_lo, __shfl_xor_sync(0xffffffffu, mx_lo, 1));
        mx_lo = fmaxf(mx_lo, __shfl_xor_sync(0xffffffffu, mx_lo, 2));
        mx_hi = fmaxf(mx_hi, __shfl_xor_sync(0xffffffffu, mx_hi, 1));
        mx_hi = fmaxf(mx_hi, __shfl_xor_sync(0xffffffffu, mx_hi, 2));
        if (tq == 0) {
            pmax[wn * 64 + r_lo] = mx_lo;
            pmax[wn * 64 + r_hi] = mx_hi;
        }
        __syncthreads();

        // phase B: exp, partial sums, stage P (fp32), rescale O
        float m_old_lo = mstate[r_lo], m_old_hi = mstate[r_hi];
        float nm_lo = fmaxf(m_old_lo, fmaxf(pmax[r_lo], pmax[64 + r_lo]));
        float nm_hi = fmaxf(m_old_hi, fmaxf(pmax[r_hi], pmax[64 + r_hi]));
        float sc_lo = __expf(m_old_lo - nm_lo);
        float sc_hi = __expf(m_old_hi - nm_hi);
        float sum_lo = 0.0f, sum_hi = 0.0f;
#pragma unroll
        for (int nf = 0; nf < 4; nf++) {
            float p0 = __expf(s[nf][0] - nm_lo);
            float p1 = __expf(s[nf][1] - nm_lo);
            float p2 = __expf(s[nf][2] - nm_hi);
            float p3 = __expf(s[nf][3] - nm_hi);
            sum_lo += p0 + p1;
            sum_hi += p2 + p3;
            int col = wn * 32 + nf * 8 + tq * 2;
            Ps[r_lo * ASTRIDE + col]     = p0;
            Ps[r_lo * ASTRIDE + col + 1] = p1;
            Ps[r_hi * ASTRIDE + col]     = p2;
            Ps[r_hi * ASTRIDE + col + 1] = p3;
        }
        sum_lo += __shfl_xor_sync(0xffffffffu, sum_lo, 1);
        sum_lo += __shfl_xor_sync(0xffffffffu, sum_lo, 2);
        sum_hi += __shfl_xor_sync(0xffffffffu, sum_hi, 1);
        sum_hi += __shfl_xor_sync(0xffffffffu, sum_hi, 2);
        if (tq == 0) {
            psum[wn * 64 + r_lo] = sum_lo;
            psum[wn * 64 + r_hi] = sum_hi;
        }
#pragma unroll
        for (int nf = 0; nf < 4; nf++) {
            o[nf][0] *= sc_lo; o[nf][1] *= sc_lo;
            o[nf][2] *= sc_hi; o[nf][3] *= sc_hi;
        }
        __syncthreads();

        if (wn == 0 && tq == 0) {
            lstate[r_lo] = lstate[r_lo] * sc_lo + psum[r_lo] + psum[64 + r_lo];
            lstate[r_hi] = lstate[r_hi] * sc_hi + psum[r_hi] + psum[64 + r_hi];
            mstate[r_lo] = nm_lo;
            mstate[r_hi] = nm_hi;
        }

        // O += P V  (split-tf32)
#pragma unroll
        for (int ks = 0; ks < 8; ks++) {
            const int c = ks * 8 + tq;
            uint32_t ph[4], pl[4];
            tfsplit(Ps[r_lo * ASTRIDE + c],     ph[0], pl[0]);
            tfsplit(Ps[r_hi * ASTRIDE + c],     ph[1], pl[1]);
            tfsplit(Ps[r_lo * ASTRIDE + c + 4], ph[2], pl[2]);
            tfsplit(Ps[r_hi * ASTRIDE + c + 4], ph[3], pl[3]);
#pragma unroll
            for (int nf = 0; nf < 4; nf++) {
                int n = wn * 32 + nf * 8 + gid;
                uint32_t bh[2], bl[2];
                tfsplit(Vs[(ks * 8 + tq) * ASTRIDE + n],     bh[0], bl[0]);
                tfsplit(Vs[(ks * 8 + tq + 4) * ASTRIDE + n], bh[1], bl[1]);
                MMA3(o[nf], ph, pl, bh, bl);
            }
        }
    }

    __syncthreads();
    float inv_lo = 1.0f / lstate[r_lo];
    float inv_hi = 1.0f / lstate[r_hi];
#pragma unroll
    for (int nf = 0; nf < 4; nf++) {
        int col = wn * 32 + nf * 8 + tq * 2;
        float2 v;
        v.x = o[nf][0] * inv_lo;
        v.y = o[nf][1] * inv_lo;
        *(float2*)&Op[base + (size_t)(q0 + r_lo) * Dv + col] = v;
        v.x = o[nf][2] * inv_hi;
        v.y = o[nf][3] * inv_hi;
        *(float2*)&Op[base + (size_t)(q0 + r_hi) * Dv + col] = v;
    }
}

// ---------------------------------------------------------------------------
extern "C" void kernel_launch(void* const* d_in, const int* in_sizes, int n_in,
                              void* d_out, int out_size)
{
    const float* q  = (const float*)d_in[0];
    const float* k  = (const float*)d_in[1];
    const float* v  = (const float*)d_in[2];
    const float* Wq = (const float*)d_in[3];
    const float* bq = (const float*)d_in[4];
    const float* Wk = (const float*)d_in[5];
    const float* bk = (const float*)d_in[6];
    const float* Wv = (const float*)d_in[7];
    const float* bv = (const float*)d_in[8];
    const float* Wo = (const float*)d_in[9];
    const float* bo = (const float*)d_in[10];
    float* out = (float*)d_out;

    float *gQ, *gK, *gV, *gA;
    cudaGetSymbolAddress((void**)&gQ, g_Q);
    cudaGetSymbolAddress((void**)&gK, g_K);
    cudaGetSymbolAddress((void**)&gV, g_V);
    cudaGetSymbolAddress((void**)&gA, g_A);

    cudaFuncSetAttribute(gemm_tc,
                         cudaFuncAttributeMaxDynamicSharedMemorySize, GSMEM);
    cudaFuncSetAttribute(attn_tc,
                         cudaFuncAttributeMaxDynamicSharedMemorySize, ASMEM);

    dim3 gg(Dv / 128, Mv / 128);  // (8, 32)
    gemm_tc<<<gg, 256, GSMEM>>>(q, Wq, bq, gQ);
    gemm_tc<<<gg, 256, GSMEM>>>(k, Wk, bk, gK);
    gemm_tc<<<gg, 256, GSMEM>>>(v, Wv, bv, gV);

    attn_tc<<<dim3(Nv / 64, Hv, Bv), 256, ASMEM>>>(gQ, gK, gV, gA);

    gemm_tc<<<gg, 256, GSMEM>>>(gA, Wo, bo, out);
}

// round 4
// speedup vs baseline: 1.5116x; 1.0688x over previous
#include <cuda_runtime.h>
#include <stdint.h>

#define Bv  2
#define Nv  2048
#define Dv  1024
#define Hv  16
#define DHv 64
#define Mv  (Bv*Nv)

// ---------------------------------------------------------------------------
// Scratch (device globals: allocation-free contract)
// ---------------------------------------------------------------------------
__device__ float g_Xh[(size_t)3 * Mv * Dv];   // split inputs q,k,v
__device__ float g_Xl[(size_t)3 * Mv * Dv];
__device__ float g_WhA[(size_t)4 * Dv * Dv];  // split Wq,Wk,Wv,Wo
__device__ float g_WlA[(size_t)4 * Dv * Dv];
__device__ float g_Qr[(size_t)Mv * Dv];       // Q projection (raw fp32)
__device__ float g_Kh[(size_t)Mv * Dv];       // K projection pre-split
__device__ float g_Kl[(size_t)Mv * Dv];
__device__ float g_Vh[(size_t)Mv * Dv];       // V projection pre-split
__device__ float g_Vl[(size_t)Mv * Dv];
__device__ float g_Ah[(size_t)Mv * Dv];       // attention output pre-split
__device__ float g_Al[(size_t)Mv * Dv];

// ---------------------------------------------------------------------------
// helpers
// ---------------------------------------------------------------------------
__device__ __forceinline__ uint32_t f2tf(float f) {
    uint32_t r;
    asm("cvt.rna.tf32.f32 %0, %1;" : "=r"(r) : "f"(f));
    return r;
}
__device__ __forceinline__ void tfsplit(float x, uint32_t& hi, uint32_t& lo) {
    hi = f2tf(x);
    lo = f2tf(x - __uint_as_float(hi));
}
__device__ __forceinline__ uint32_t f2u(float f) { return __float_as_uint(f); }
__device__ __forceinline__ float u2f(uint32_t u) { return __uint_as_float(u); }

#define MMA_TF32(d, a0, a1, a2, a3, b0, b1)                                   \
    asm volatile(                                                             \
        "mma.sync.aligned.m16n8k8.row.col.f32.tf32.tf32.f32 "                 \
        "{%0,%1,%2,%3},{%4,%5,%6,%7},{%8,%9},{%0,%1,%2,%3};"                  \
        : "+f"(d[0]), "+f"(d[1]), "+f"(d[2]), "+f"(d[3])                      \
        : "r"(a0), "r"(a1), "r"(a2), "r"(a3), "r"(b0), "r"(b1))

#define MMA3(d, ah, al, bh, bl)                                               \
    MMA_TF32(d, ah[0], ah[1], ah[2], ah[3], bh[0], bh[1]);                    \
    MMA_TF32(d, ah[0], ah[1], ah[2], ah[3], bl[0], bl[1]);                    \
    MMA_TF32(d, al[0], al[1], al[2], al[3], bh[0], bh[1]);

__device__ __forceinline__ void cp_async16(uint32_t daddr, const void* src) {
    asm volatile("cp.async.cg.shared.global [%0], [%1], 16;"
                 :: "r"(daddr), "l"(src));
}

// ---------------------------------------------------------------------------
// prepass: split tensors into tf32 hi/lo (bandwidth-bound, DRAM is idle)
// ---------------------------------------------------------------------------
__device__ __forceinline__ void split4_store(float4 v, float* hi, float* lo,
                                             size_t idx) {
    uint32_t h, l;
    float4 vh, vl;
    tfsplit(v.x, h, l); vh.x = u2f(h); vl.x = u2f(l);
    tfsplit(v.y, h, l); vh.y = u2f(h); vl.y = u2f(l);
    tfsplit(v.z, h, l); vh.z = u2f(h); vl.z = u2f(l);
    tfsplit(v.w, h, l); vh.w = u2f(h); vl.w = u2f(l);
    *(float4*)(hi + idx) = vh;
    *(float4*)(lo + idx) = vl;
}

__global__ __launch_bounds__(256) void split3_kernel(
    const float* __restrict__ a, const float* __restrict__ b,
    const float* __restrict__ c, float* __restrict__ hi,
    float* __restrict__ lo)
{
    const float* src = (blockIdx.y == 0) ? a : (blockIdx.y == 1) ? b : c;
    size_t off = (size_t)blockIdx.y * Mv * Dv;
    size_t i = ((size_t)blockIdx.x * 256 + threadIdx.x) * 4;
    split4_store(*(const float4*)(src + i), hi, lo, off + i);
}

__global__ __launch_bounds__(256) void splitW_kernel(
    const float* __restrict__ w0, const float* __restrict__ w1,
    const float* __restrict__ w2, const float* __restrict__ w3,
    float* __restrict__ hi, float* __restrict__ lo)
{
    const float* src = (blockIdx.y == 0) ? w0 : (blockIdx.y == 1) ? w1
                     : (blockIdx.y == 2) ? w2 : w3;
    size_t off = (size_t)blockIdx.y * Dv * Dv;
    size_t i = ((size_t)blockIdx.x * 256 + threadIdx.x) * 4;
    split4_store(*(const float4*)(src + i), hi, lo, off + i);
}

// ---------------------------------------------------------------------------
// GEMM: Y[m,n] = sum_k X[m,k]*W[n,k] + bias[n], pre-split operands.
// CTA 128x128, Kc=16, split-tf32 (3 MMAs), cp.async double buffer.
// stride 20: bank = (20*gid + tq(+4))%32 -> all 32 distinct, conflict-free.
// Epilogue: raw store (Yr) OR split store (Yh/Yl).
// ---------------------------------------------------------------------------
#define GK      16
#define GSTRIDE 20
#define GTILE   (128 * GSTRIDE)
#define GSMEM   (8 * GTILE * 4)

__global__ __launch_bounds__(256, 2) void gemm_tc(
    const float* __restrict__ Xh, const float* __restrict__ Xl,
    const float* __restrict__ Wh, const float* __restrict__ Wl,
    const float* __restrict__ bias,
    float* __restrict__ Yr, float* __restrict__ Yh, float* __restrict__ Yl)
{
    extern __shared__ float sm[];
    float* Ah = sm;               // [2][128][20]
    float* Al = Ah + 2 * GTILE;
    float* Bh = Al + 2 * GTILE;
    float* Bl = Bh + 2 * GTILE;

    const int t    = threadIdx.x;
    const int lane = t & 31;
    const int warp = t >> 5;
    const int gid  = lane >> 2;
    const int tq   = lane & 3;
    const int wm   = warp >> 2;   // 0..1
    const int wn   = warp & 3;    // 0..3
    const int m0   = blockIdx.y * 128;
    const int n0   = blockIdx.x * 128;

    const uint32_t sbase = (uint32_t)__cvta_generic_to_shared(sm);

    float acc[4][4][4];
#pragma unroll
    for (int mf = 0; mf < 4; mf++)
#pragma unroll
        for (int nf = 0; nf < 4; nf++)
#pragma unroll
            for (int c = 0; c < 4; c++) acc[mf][nf][c] = 0.0f;

#define GEMM_ISSUE(buf, k0)                                                    \
    {                                                                          \
        _Pragma("unroll")                                                      \
        for (int i = 0; i < 2; i++) {                                          \
            int idx = t + i * 256;                                             \
            int row = idx >> 2;                                                \
            int c4  = (idx & 3) << 2;                                          \
            size_t gx = (size_t)(m0 + row) * Dv + (k0) + c4;                   \
            size_t gw = (size_t)(n0 + row) * Dv + (k0) + c4;                   \
            uint32_t so = ((buf) * GTILE + row * GSTRIDE + c4) * 4;            \
            cp_async16(sbase + so,                   Xh + gx);                 \
            cp_async16(sbase + 2 * GTILE * 4 + so,   Xl + gx);                 \
            cp_async16(sbase + 4 * GTILE * 4 + so,   Wh + gw);                 \
            cp_async16(sbase + 6 * GTILE * 4 + so,   Wl + gw);                 \
        }                                                                      \
        asm volatile("cp.async.commit_group;");                                \
    }

    GEMM_ISSUE(0, 0);

    for (int it = 0; it < Dv / GK; it++) {
        asm volatile("cp.async.wait_group 0;" ::: "memory");
        __syncthreads();
        if (it + 1 < Dv / GK) GEMM_ISSUE((it + 1) & 1, (it + 1) * GK);

        const float* Ahp = Ah + (it & 1) * GTILE;
        const float* Alp = Al + (it & 1) * GTILE;
        const float* Bhp = Bh + (it & 1) * GTILE;
        const float* Blp = Bl + (it & 1) * GTILE;

#pragma unroll
        for (int ks = 0; ks < 2; ks++) {
            const int c = ks * 8 + tq;
            uint32_t ah[4][4], al[4][4];
#pragma unroll
            for (int mf = 0; mf < 4; mf++) {
                int r = wm * 64 + mf * 16 + gid;
                ah[mf][0] = f2u(Ahp[r * GSTRIDE + c]);
                ah[mf][1] = f2u(Ahp[(r + 8) * GSTRIDE + c]);
                ah[mf][2] = f2u(Ahp[r * GSTRIDE + c + 4]);
                ah[mf][3] = f2u(Ahp[(r + 8) * GSTRIDE + c + 4]);
                al[mf][0] = f2u(Alp[r * GSTRIDE + c]);
                al[mf][1] = f2u(Alp[(r + 8) * GSTRIDE + c]);
                al[mf][2] = f2u(Alp[r * GSTRIDE + c + 4]);
                al[mf][3] = f2u(Alp[(r + 8) * GSTRIDE + c + 4]);
            }
#pragma unroll
            for (int nf = 0; nf < 4; nf++) {
                int n = wn * 32 + nf * 8 + gid;
                uint32_t bh[2], bl[2];
                bh[0] = f2u(Bhp[n * GSTRIDE + c]);
                bh[1] = f2u(Bhp[n * GSTRIDE + c + 4]);
                bl[0] = f2u(Blp[n * GSTRIDE + c]);
                bl[1] = f2u(Blp[n * GSTRIDE + c + 4]);
#pragma unroll
                for (int mf = 0; mf < 4; mf++) {
                    MMA3(acc[mf][nf], ah[mf], al[mf], bh, bl);
                }
            }
        }
    }

    // epilogue
#pragma unroll
    for (int nf = 0; nf < 4; nf++) {
        int col = n0 + wn * 32 + nf * 8 + tq * 2;
        float2 bb = *(const float2*)&bias[col];
#pragma unroll
        for (int mf = 0; mf < 4; mf++) {
            int r = m0 + wm * 64 + mf * 16 + gid;
            float v0 = acc[mf][nf][0] + bb.x;
            float v1 = acc[mf][nf][1] + bb.y;
            float v2 = acc[mf][nf][2] + bb.x;
            float v3 = acc[mf][nf][3] + bb.y;
            if (Yr) {
                *(float2*)&Yr[(size_t)r * Dv + col]       = make_float2(v0, v1);
                *(float2*)&Yr[(size_t)(r + 8) * Dv + col] = make_float2(v2, v3);
            } else {
                uint32_t h0, l0, h1, l1;
                tfsplit(v0, h0, l0); tfsplit(v1, h1, l1);
                *(float2*)&Yh[(size_t)r * Dv + col] = make_float2(u2f(h0), u2f(h1));
                *(float2*)&Yl[(size_t)r * Dv + col] = make_float2(u2f(l0), u2f(l1));
                tfsplit(v2, h0, l0); tfsplit(v3, h1, l1);
                *(float2*)&Yh[(size_t)(r + 8) * Dv + col] = make_float2(u2f(h0), u2f(h1));
                *(float2*)&Yl[(size_t)(r + 8) * Dv + col] = make_float2(u2f(l0), u2f(l1));
            }
        }
    }
}

// ---------------------------------------------------------------------------
// Flash attention, split-tf32 with pre-split K/V from gmem (cp.async).
// CTA: 64 q-rows, 8 warps (4 wm x 2 wn). Q raw in regs (split per use),
// P split once at creation into Psh/Psl. K/P stride 68, V stride 72
// ((8*tq+gid)%32 distinct -> conflict-free V b-frags).
// ---------------------------------------------------------------------------
#define AS 68
#define VS 72
#define AT (64 * AS)
#define VT (64 * VS)
#define ASMEM ((4 * AT + 2 * VT + 64 + 64 + 128 + 128) * 4)

__global__ __launch_bounds__(256, 2) void attn_tc(
    const float* __restrict__ Qr,
    const float* __restrict__ Kh, const float* __restrict__ Kl,
    const float* __restrict__ Vh, const float* __restrict__ Vl,
    float* __restrict__ Oh, float* __restrict__ Ol)
{
    extern __shared__ float sm[];
    float* Ksh    = sm;                // [64][68]
    float* Ksl    = Ksh + AT;          // [64][68]
    float* Psh    = Ksl + AT;          // [64][68]  (Q staging at start)
    float* Psl    = Psh + AT;          // [64][68]
    float* Vsh    = Psl + AT;          // [64][72]
    float* Vsl    = Vsh + VT;          // [64][72]
    float* mstate = Vsl + VT;          // [64]
    float* lstate = mstate + 64;       // [64]
    float* pmax   = lstate + 64;       // [2][64]
    float* psum   = pmax + 128;        // [2][64]

    const int t    = threadIdx.x;
    const int lane = t & 31;
    const int warp = t >> 5;
    const int gid  = lane >> 2;
    const int tq   = lane & 3;
    const int wm   = warp >> 1;   // 0..3
    const int wn   = warp & 1;    // 0..1
    const int q0   = blockIdx.x * 64;
    const size_t base =
        (size_t)blockIdx.z * Nv * Dv + (size_t)blockIdx.y * DHv;

    const uint32_t sb = (uint32_t)__cvta_generic_to_shared(sm);
    const uint32_t sbKh = sb;
    const uint32_t sbKl = sb + AT * 4;
    const uint32_t sbVh = sb + 4 * AT * 4;
    const uint32_t sbVl = sb + (4 * AT + VT) * 4;

    // stage Q (raw) into Psh, init state
#pragma unroll
    for (int i = 0; i < 1; i++) {
        int idx = t;
        int r   = idx >> 2;
        int c4  = (idx & 3) << 4;  // 4 float4 per row of 64
        // 64 rows x 64 floats = 256 float4 -> one per thread
        float4 v = *(const float4*)&Qr[base + (size_t)(q0 + r) * Dv + (idx & 3) * 16 / 4];
        (void)c4; (void)v;
    }
    // simpler exact mapping: 1024 float4-chunks? use 4-iter float4 loop:
#pragma unroll
    for (int i = 0; i < 4; i++) {
        int idx = t + i * 256;          // [0,1024)
        int r   = idx >> 4;
        int c4  = (idx & 15) << 2;
        float4 v = *(const float4*)&Qr[base + (size_t)(q0 + r) * Dv + c4];
        *(float4*)&Psh[r * AS + c4] = v;
    }
    if (t < 64) { mstate[t] = -1e30f; lstate[t] = 0.0f; }
    __syncthreads();

    // Q fragments (raw fp32) -> registers
    float qf[8][4];
    {
        const int r = wm * 16 + gid;
#pragma unroll
        for (int ks = 0; ks < 8; ks++) {
            int c = ks * 8 + tq;
            qf[ks][0] = Psh[r * AS + c];
            qf[ks][1] = Psh[(r + 8) * AS + c];
            qf[ks][2] = Psh[r * AS + c + 4];
            qf[ks][3] = Psh[(r + 8) * AS + c + 4];
        }
    }

    float o[4][4];
#pragma unroll
    for (int nf = 0; nf < 4; nf++)
#pragma unroll
        for (int c = 0; c < 4; c++) o[nf][c] = 0.0f;

    const int r_lo = wm * 16 + gid;
    const int r_hi = r_lo + 8;

    for (int kt = 0; kt < Nv / 64; kt++) {
        __syncthreads();   // previous tile fully consumed (incl. Psh=Q frags)
        // cp.async pre-split K/V tiles
#pragma unroll
        for (int i = 0; i < 4; i++) {
            int idx = t + i * 256;      // [0,1024)
            int r   = idx >> 4;
            int c4  = (idx & 15) << 2;
            size_t g = base + (size_t)(kt * 64 + r) * Dv + c4;
            cp_async16(sbKh + (r * AS + c4) * 4, Kh + g);
            cp_async16(sbKl + (r * AS + c4) * 4, Kl + g);
            cp_async16(sbVh + (r * VS + c4) * 4, Vh + g);
            cp_async16(sbVl + (r * VS + c4) * 4, Vl + g);
        }
        asm volatile("cp.async.commit_group;");
        asm volatile("cp.async.wait_group 0;" ::: "memory");
        __syncthreads();

        // S = Q K^T (split-tf32; Q split inline, K pre-split)
        float s[4][4];
#pragma unroll
        for (int nf = 0; nf < 4; nf++)
#pragma unroll
            for (int c = 0; c < 4; c++) s[nf][c] = 0.0f;
#pragma unroll
        for (int ks = 0; ks < 8; ks++) {
            const int c = ks * 8 + tq;
            uint32_t qh[4], ql[4];
#pragma unroll
            for (int e = 0; e < 4; e++) tfsplit(qf[ks][e], qh[e], ql[e]);
#pragma unroll
            for (int nf = 0; nf < 4; nf++) {
                int n = wn * 32 + nf * 8 + gid;
                uint32_t bh[2], bl[2];
                bh[0] = f2u(Ksh[n * AS + c]);
                bh[1] = f2u(Ksh[n * AS + c + 4]);
                bl[0] = f2u(Ksl[n * AS + c]);
                bl[1] = f2u(Ksl[n * AS + c + 4]);
                MMA3(s[nf], qh, ql, bh, bl);
            }
        }

        // phase A: per-row max
        float mx_lo = -1e30f, mx_hi = -1e30f;
#pragma unroll
        for (int nf = 0; nf < 4; nf++) {
            mx_lo = fmaxf(mx_lo, fmaxf(s[nf][0], s[nf][1]));
            mx_hi = fmaxf(mx_hi, fmaxf(s[nf][2], s[nf][3]));
        }
        mx_lo = fmaxf(mx_lo, __shfl_xor_sync(0xffffffffu, mx_lo, 1));
        mx_lo = fmaxf(mx_lo, __shfl_xor_sync(0xffffffffu, mx_lo, 2));
        mx_hi = fmaxf(mx_hi, __shfl_xor_sync(0xffffffffu, mx_hi, 1));
        mx_hi = fmaxf(mx_hi, __shfl_xor_sync(0xffffffffu, mx_hi, 2));
        if (tq == 0) {
            pmax[wn * 64 + r_lo] = mx_lo;
            pmax[wn * 64 + r_hi] = mx_hi;
        }
        __syncthreads();

        // phase B: exp, sums, stage P split-once, rescale O
        float m_old_lo = mstate[r_lo], m_old_hi = mstate[r_hi];
        float nm_lo = fmaxf(m_old_lo, fmaxf(pmax[r_lo], pmax[64 + r_lo]));
        float nm_hi = fmaxf(m_old_hi, fmaxf(pmax[r_hi], pmax[64 + r_hi]));
        float sc_lo = __expf(m_old_lo - nm_lo);
        float sc_hi = __expf(m_old_hi - nm_hi);
        float sum_lo = 0.0f, sum_hi = 0.0f;
#pragma unroll
        for (int nf = 0; nf < 4; nf++) {
            float p0 = __expf(s[nf][0] - nm_lo);
            float p1 = __expf(s[nf][1] - nm_lo);
            float p2 = __expf(s[nf][2] - nm_hi);
            float p3 = __expf(s[nf][3] - nm_hi);
            sum_lo += p0 + p1;
            sum_hi += p2 + p3;
            int col = wn * 32 + nf * 8 + tq * 2;
            uint32_t h, l;
            tfsplit(p0, h, l);
            Psh[r_lo * AS + col] = u2f(h);     Psl[r_lo * AS + col] = u2f(l);
            tfsplit(p1, h, l);
            Psh[r_lo * AS + col + 1] = u2f(h); Psl[r_lo * AS + col + 1] = u2f(l);
            tfsplit(p2, h, l);
            Psh[r_hi * AS + col] = u2f(h);     Psl[r_hi * AS + col] = u2f(l);
            tfsplit(p3, h, l);
            Psh[r_hi * AS + col + 1] = u2f(h); Psl[r_hi * AS + col + 1] = u2f(l);
        }
        sum_lo += __shfl_xor_sync(0xffffffffu, sum_lo, 1);
        sum_lo += __shfl_xor_sync(0xffffffffu, sum_lo, 2);
        sum_hi += __shfl_xor_sync(0xffffffffu, sum_hi, 1);
        sum_hi += __shfl_xor_sync(0xffffffffu, sum_hi, 2);
        if (tq == 0) {
            psum[wn * 64 + r_lo] = sum_lo;
            psum[wn * 64 + r_hi] = sum_hi;
        }
#pragma unroll
        for (int nf = 0; nf < 4; nf++) {
            o[nf][0] *= sc_lo; o[nf][1] *= sc_lo;
            o[nf][2] *= sc_hi; o[nf][3] *= sc_hi;
        }
        __syncthreads();

        if (wn == 0 && tq == 0) {
            lstate[r_lo] = lstate[r_lo] * sc_lo + psum[r_lo] + psum[64 + r_lo];
            lstate[r_hi] = lstate[r_hi] * sc_hi + psum[r_hi] + psum[64 + r_hi];
            mstate[r_lo] = nm_lo;
            mstate[r_hi] = nm_hi;
        }

        // O += P V (both pre-split)
#pragma unroll
        for (int ks = 0; ks < 8; ks++) {
            const int c = ks * 8 + tq;
            uint32_t ph[4], pl[4];
            ph[0] = f2u(Psh[r_lo * AS + c]);
            ph[1] = f2u(Psh[r_hi * AS + c]);
            ph[2] = f2u(Psh[r_lo * AS + c + 4]);
            ph[3] = f2u(Psh[r_hi * AS + c + 4]);
            pl[0] = f2u(Psl[r_lo * AS + c]);
            pl[1] = f2u(Psl[r_hi * AS + c]);
            pl[2] = f2u(Psl[r_lo * AS + c + 4]);
            pl[3] = f2u(Psl[r_hi * AS + c + 4]);
#pragma unroll
            for (int nf = 0; nf < 4; nf++) {
                int n = wn * 32 + nf * 8 + gid;
                uint32_t bh[2], bl[2];
                bh[0] = f2u(Vsh[(ks * 8 + tq) * VS + n]);
                bh[1] = f2u(Vsh[(ks * 8 + tq + 4) * VS + n]);
                bl[0] = f2u(Vsl[(ks * 8 + tq) * VS + n]);
                bl[1] = f2u(Vsl[(ks * 8 + tq + 4) * VS + n]);
                MMA3(o[nf], ph, pl, bh, bl);
            }
        }
    }

    __syncthreads();
    float inv_lo = 1.0f / lstate[r_lo];
    float inv_hi = 1.0f / lstate[r_hi];
#pragma unroll
    for (int nf = 0; nf < 4; nf++) {
        int col = wn * 32 + nf * 8 + tq * 2;
        uint32_t h0, l0, h1, l1;
        float v0 = o[nf][0] * inv_lo, v1 = o[nf][1] * inv_lo;
        tfsplit(v0, h0, l0); tfsplit(v1, h1, l1);
        size_t glo = base + (size_t)(q0 + r_lo) * Dv + col;
        *(float2*)&Oh[glo] = make_float2(u2f(h0), u2f(h1));
        *(float2*)&Ol[glo] = make_float2(u2f(l0), u2f(l1));
        float v2 = o[nf][2] * inv_hi, v3 = o[nf][3] * inv_hi;
        tfsplit(v2, h0, l0); tfsplit(v3, h1, l1);
        size_t ghi = base + (size_t)(q0 + r_hi) * Dv + col;
        *(float2*)&Oh[ghi] = make_float2(u2f(h0), u2f(h1));
        *(float2*)&Ol[ghi] = make_float2(u2f(l0), u2f(l1));
    }
}

// ---------------------------------------------------------------------------
extern "C" void kernel_launch(void* const* d_in, const int* in_sizes, int n_in,
                              void* d_out, int out_size)
{
    const float* q  = (const float*)d_in[0];
    const float* k  = (const float*)d_in[1];
    const float* v  = (const float*)d_in[2];
    const float* Wq = (const float*)d_in[3];
    const float* bq = (const float*)d_in[4];
    const float* Wk = (const float*)d_in[5];
    const float* bk = (const float*)d_in[6];
    const float* Wv = (const float*)d_in[7];
    const float* bv = (const float*)d_in[8];
    const float* Wo = (const float*)d_in[9];
    const float* bo = (const float*)d_in[10];
    float* out = (float*)d_out;

    float *xh, *xl, *wh, *wl, *qr, *kh, *kl, *vh, *vl, *ah, *al;
    cudaGetSymbolAddress((void**)&xh, g_Xh);
    cudaGetSymbolAddress((void**)&xl, g_Xl);
    cudaGetSymbolAddress((void**)&wh, g_WhA);
    cudaGetSymbolAddress((void**)&wl, g_WlA);
    cudaGetSymbolAddress((void**)&qr, g_Qr);
    cudaGetSymbolAddress((void**)&kh, g_Kh);
    cudaGetSymbolAddress((void**)&kl, g_Kl);
    cudaGetSymbolAddress((void**)&vh, g_Vh);
    cudaGetSymbolAddress((void**)&vl, g_Vl);
    cudaGetSymbolAddress((void**)&ah, g_Ah);
    cudaGetSymbolAddress((void**)&al, g_Al);

    cudaFuncSetAttribute(gemm_tc,
                         cudaFuncAttributeMaxDynamicSharedMemorySize, GSMEM);
    cudaFuncSetAttribute(attn_tc,
                         cudaFuncAttributeMaxDynamicSharedMemorySize, ASMEM);

    const size_t TD = (size_t)Mv * Dv;
    const size_t WD = (size_t)Dv * Dv;

    split3_kernel<<<dim3(4096, 3), 256>>>(q, k, v, xh, xl);
    splitW_kernel<<<dim3(1024, 4), 256>>>(Wq, Wk, Wv, Wo, wh, wl);

    dim3 gg(Dv / 128, Mv / 128);  // (8, 32)
    gemm_tc<<<gg, 256, GSMEM>>>(xh,          xl,          wh,          wl,
                                bq, qr, nullptr, nullptr);
    gemm_tc<<<gg, 256, GSMEM>>>(xh + TD,     xl + TD,     wh + WD,     wl + WD,
                                bk, nullptr, kh, kl);
    gemm_tc<<<gg, 256, GSMEM>>>(xh + 2 * TD, xl + 2 * TD, wh + 2 * WD, wl + 2 * WD,
                                bv, nullptr, vh, vl);

    attn_tc<<<dim3(Nv / 64, Hv, Bv), 256, ASMEM>>>(qr, kh, kl, vh, vl, ah, al);

    gemm_tc<<<gg, 256, GSMEM>>>(ah, al, wh + 3 * WD, wl + 3 * WD,
                                bo, out, nullptr, nullptr);
}

// round 5
// speedup vs baseline: 1.5883x; 1.0508x over previous
#include <cuda_runtime.h>
#include <stdint.h>

#define Bv  2
#define Nv  2048
#define Dv  1024
#define Hv  16
#define DHv 64
#define Mv  (Bv*Nv)

// ---------------------------------------------------------------------------
// Scratch (device globals: allocation-free contract)
// ---------------------------------------------------------------------------
__device__ float g_Xh[(size_t)3 * Mv * Dv];   // split inputs q,k,v
__device__ float g_Xl[(size_t)3 * Mv * Dv];
__device__ float g_WhA[(size_t)4 * Dv * Dv];  // split Wq,Wk,Wv,Wo
__device__ float g_WlA[(size_t)4 * Dv * Dv];
__device__ float g_Qr[(size_t)Mv * Dv];       // Q projection (raw fp32)
__device__ float g_Kh[(size_t)Mv * Dv];       // K projection pre-split
__device__ float g_Kl[(size_t)Mv * Dv];
__device__ float g_Vh[(size_t)Mv * Dv];       // V projection pre-split
__device__ float g_Vl[(size_t)Mv * Dv];
__device__ float g_Ah[(size_t)Mv * Dv];       // attention output pre-split
__device__ float g_Al[(size_t)Mv * Dv];

// ---------------------------------------------------------------------------
// helpers
// ---------------------------------------------------------------------------
__device__ __forceinline__ uint32_t f2tf(float f) {
    uint32_t r;
    asm("cvt.rna.tf32.f32 %0, %1;" : "=r"(r) : "f"(f));
    return r;
}
__device__ __forceinline__ void tfsplit(float x, uint32_t& hi, uint32_t& lo) {
    hi = f2tf(x);
    lo = f2tf(x - __uint_as_float(hi));
}
__device__ __forceinline__ uint32_t f2u(float f) { return __float_as_uint(f); }
__device__ __forceinline__ float u2f(uint32_t u) { return __uint_as_float(u); }

#define MMA_TF32(d, a0, a1, a2, a3, b0, b1)                                   \
    asm volatile(                                                             \
        "mma.sync.aligned.m16n8k8.row.col.f32.tf32.tf32.f32 "                 \
        "{%0,%1,%2,%3},{%4,%5,%6,%7},{%8,%9},{%0,%1,%2,%3};"                  \
        : "+f"(d[0]), "+f"(d[1]), "+f"(d[2]), "+f"(d[3])                      \
        : "r"(a0), "r"(a1), "r"(a2), "r"(a3), "r"(b0), "r"(b1))

#define MMA3(d, ah, al, bh, bl)                                               \
    MMA_TF32(d, ah[0], ah[1], ah[2], ah[3], bh[0], bh[1]);                    \
    MMA_TF32(d, ah[0], ah[1], ah[2], ah[3], bl[0], bl[1]);                    \
    MMA_TF32(d, al[0], al[1], al[2], al[3], bh[0], bh[1]);

__device__ __forceinline__ void cp_async16(uint32_t daddr, const void* src) {
    asm volatile("cp.async.cg.shared.global [%0], [%1], 16;"
                 :: "r"(daddr), "l"(src));
}

// ---------------------------------------------------------------------------
// prepass: split tensors into tf32 hi/lo (bandwidth-bound, DRAM is idle)
// ---------------------------------------------------------------------------
__device__ __forceinline__ void split4_store(float4 v, float* hi, float* lo,
                                             size_t idx) {
    uint32_t h, l;
    float4 vh, vl;
    tfsplit(v.x, h, l); vh.x = u2f(h); vl.x = u2f(l);
    tfsplit(v.y, h, l); vh.y = u2f(h); vl.y = u2f(l);
    tfsplit(v.z, h, l); vh.z = u2f(h); vl.z = u2f(l);
    tfsplit(v.w, h, l); vh.w = u2f(h); vl.w = u2f(l);
    *(float4*)(hi + idx) = vh;
    *(float4*)(lo + idx) = vl;
}

__global__ __launch_bounds__(256) void split3_kernel(
    const float* __restrict__ a, const float* __restrict__ b,
    const float* __restrict__ c, float* __restrict__ hi,
    float* __restrict__ lo)
{
    const float* src = (blockIdx.y == 0) ? a : (blockIdx.y == 1) ? b : c;
    size_t off = (size_t)blockIdx.y * Mv * Dv;
    size_t i = ((size_t)blockIdx.x * 256 + threadIdx.x) * 4;
    split4_store(*(const float4*)(src + i), hi, lo, off + i);
}

__global__ __launch_bounds__(256) void splitW_kernel(
    const float* __restrict__ w0, const float* __restrict__ w1,
    const float* __restrict__ w2, const float* __restrict__ w3,
    float* __restrict__ hi, float* __restrict__ lo)
{
    const float* src = (blockIdx.y == 0) ? w0 : (blockIdx.y == 1) ? w1
                     : (blockIdx.y == 2) ? w2 : w3;
    size_t off = (size_t)blockIdx.y * Dv * Dv;
    size_t i = ((size_t)blockIdx.x * 256 + threadIdx.x) * 4;
    split4_store(*(const float4*)(src + i), hi, lo, off + i);
}

// ---------------------------------------------------------------------------
// GEMM body: Y[m,n] = sum_k X[m,k]*W[n,k] + bias[n], pre-split operands.
// CTA 128x128, Kc=16, split-tf32 (3 MMAs), cp.async double buffer.
// stride 20 -> conflict-free fragment LDS (verified bank math).
// ---------------------------------------------------------------------------
#define GK      16
#define GSTRIDE 20
#define GTILE   (128 * GSTRIDE)
#define GSMEM   (8 * GTILE * 4)

__device__ __forceinline__ void gemm_body(
    const float* __restrict__ Xh, const float* __restrict__ Xl,
    const float* __restrict__ Wh, const float* __restrict__ Wl,
    const float* __restrict__ bias,
    float* __restrict__ Yr, float* __restrict__ Yh, float* __restrict__ Yl,
    int m0, int n0)
{
    extern __shared__ float sm[];
    float* Ah = sm;               // [2][128][20]
    float* Al = Ah + 2 * GTILE;
    float* Bh = Al + 2 * GTILE;
    float* Bl = Bh + 2 * GTILE;

    const int t    = threadIdx.x;
    const int lane = t & 31;
    const int warp = t >> 5;
    const int gid  = lane >> 2;
    const int tq   = lane & 3;
    const int wm   = warp >> 2;   // 0..1
    const int wn   = warp & 3;    // 0..3

    const uint32_t sbase = (uint32_t)__cvta_generic_to_shared(sm);

    float acc[4][4][4];
#pragma unroll
    for (int mf = 0; mf < 4; mf++)
#pragma unroll
        for (int nf = 0; nf < 4; nf++)
#pragma unroll
            for (int c = 0; c < 4; c++) acc[mf][nf][c] = 0.0f;

#define GEMM_ISSUE(buf, k0)                                                    \
    {                                                                          \
        _Pragma("unroll")                                                      \
        for (int i = 0; i < 2; i++) {                                          \
            int idx = t + i * 256;                                             \
            int row = idx >> 2;                                                \
            int c4  = (idx & 3) << 2;                                          \
            size_t gx = (size_t)(m0 + row) * Dv + (k0) + c4;                   \
            size_t gw = (size_t)(n0 + row) * Dv + (k0) + c4;                   \
            uint32_t so = ((buf) * GTILE + row * GSTRIDE + c4) * 4;            \
            cp_async16(sbase + so,                   Xh + gx);                 \
            cp_async16(sbase + 2 * GTILE * 4 + so,   Xl + gx);                 \
            cp_async16(sbase + 4 * GTILE * 4 + so,   Wh + gw);                 \
            cp_async16(sbase + 6 * GTILE * 4 + so,   Wl + gw);                 \
        }                                                                      \
        asm volatile("cp.async.commit_group;");                                \
    }

    GEMM_ISSUE(0, 0);

    for (int it = 0; it < Dv / GK; it++) {
        asm volatile("cp.async.wait_group 0;" ::: "memory");
        __syncthreads();
        if (it + 1 < Dv / GK) GEMM_ISSUE((it + 1) & 1, (it + 1) * GK);

        const float* Ahp = Ah + (it & 1) * GTILE;
        const float* Alp = Al + (it & 1) * GTILE;
        const float* Bhp = Bh + (it & 1) * GTILE;
        const float* Blp = Bl + (it & 1) * GTILE;

#pragma unroll
        for (int ks = 0; ks < 2; ks++) {
            const int c = ks * 8 + tq;
            uint32_t ah[4][4], al[4][4];
#pragma unroll
            for (int mf = 0; mf < 4; mf++) {
                int r = wm * 64 + mf * 16 + gid;
                ah[mf][0] = f2u(Ahp[r * GSTRIDE + c]);
                ah[mf][1] = f2u(Ahp[(r + 8) * GSTRIDE + c]);
                ah[mf][2] = f2u(Ahp[r * GSTRIDE + c + 4]);
                ah[mf][3] = f2u(Ahp[(r + 8) * GSTRIDE + c + 4]);
                al[mf][0] = f2u(Alp[r * GSTRIDE + c]);
                al[mf][1] = f2u(Alp[(r + 8) * GSTRIDE + c]);
                al[mf][2] = f2u(Alp[r * GSTRIDE + c + 4]);
                al[mf][3] = f2u(Alp[(r + 8) * GSTRIDE + c + 4]);
            }
#pragma unroll
            for (int nf = 0; nf < 4; nf++) {
                int n = wn * 32 + nf * 8 + gid;
                uint32_t bh[2], bl[2];
                bh[0] = f2u(Bhp[n * GSTRIDE + c]);
                bh[1] = f2u(Bhp[n * GSTRIDE + c + 4]);
                bl[0] = f2u(Blp[n * GSTRIDE + c]);
                bl[1] = f2u(Blp[n * GSTRIDE + c + 4]);
#pragma unroll
                for (int mf = 0; mf < 4; mf++) {
                    MMA3(acc[mf][nf], ah[mf], al[mf], bh, bl);
                }
            }
        }
    }

    // epilogue
#pragma unroll
    for (int nf = 0; nf < 4; nf++) {
        int col = n0 + wn * 32 + nf * 8 + tq * 2;
        float2 bb = *(const float2*)&bias[col];
#pragma unroll
        for (int mf = 0; mf < 4; mf++) {
            int r = m0 + wm * 64 + mf * 16 + gid;
            float v0 = acc[mf][nf][0] + bb.x;
            float v1 = acc[mf][nf][1] + bb.y;
            float v2 = acc[mf][nf][2] + bb.x;
            float v3 = acc[mf][nf][3] + bb.y;
            if (Yr) {
                *(float2*)&Yr[(size_t)r * Dv + col]       = make_float2(v0, v1);
                *(float2*)&Yr[(size_t)(r + 8) * Dv + col] = make_float2(v2, v3);
            } else {
                uint32_t h0, l0, h1, l1;
                tfsplit(v0, h0, l0); tfsplit(v1, h1, l1);
                *(float2*)&Yh[(size_t)r * Dv + col] = make_float2(u2f(h0), u2f(h1));
                *(float2*)&Yl[(size_t)r * Dv + col] = make_float2(u2f(l0), u2f(l1));
                tfsplit(v2, h0, l0); tfsplit(v3, h1, l1);
                *(float2*)&Yh[(size_t)(r + 8) * Dv + col] = make_float2(u2f(h0), u2f(h1));
                *(float2*)&Yl[(size_t)(r + 8) * Dv + col] = make_float2(u2f(l0), u2f(l1));
            }
        }
    }
}

// fused QKV projection: grid.z selects q/k/v
__global__ __launch_bounds__(256, 2) void gemm_qkv(
    const float* __restrict__ Xh, const float* __restrict__ Xl,
    const float* __restrict__ Wh, const float* __restrict__ Wl,
    const float* __restrict__ bq, const float* __restrict__ bk,
    const float* __restrict__ bv,
    float* __restrict__ Qr,
    float* __restrict__ Kh, float* __restrict__ Kl,
    float* __restrict__ Vh, float* __restrict__ Vl)
{
    const int z = blockIdx.z;
    const float* xh = Xh + (size_t)z * Mv * Dv;
    const float* xl = Xl + (size_t)z * Mv * Dv;
    const float* wh = Wh + (size_t)z * Dv * Dv;
    const float* wl = Wl + (size_t)z * Dv * Dv;
    const float* bias = (z == 0) ? bq : (z == 1) ? bk : bv;
    float* yr = (z == 0) ? Qr : nullptr;
    float* yh = (z == 1) ? Kh : Vh;
    float* yl = (z == 1) ? Kl : Vl;
    gemm_body(xh, xl, wh, wl, bias, yr, yh, yl,
              blockIdx.y * 128, blockIdx.x * 128);
}

// output projection (raw store)
__global__ __launch_bounds__(256, 2) void gemm_out(
    const float* __restrict__ Xh, const float* __restrict__ Xl,
    const float* __restrict__ Wh, const float* __restrict__ Wl,
    const float* __restrict__ bias, float* __restrict__ Yr)
{
    gemm_body(Xh, Xl, Wh, Wl, bias, Yr, nullptr, nullptr,
              blockIdx.y * 128, blockIdx.x * 128);
}

// ---------------------------------------------------------------------------
// Flash attention, split-tf32, pre-split K/V, Q split hoisted to registers,
// cross-phase cp.async pipelining:
//   K(kt+1) issued after S-phase barrier (overlaps softmax+PV),
//   V(kt+1) issued after PV barrier (overlaps next S+softmax).
// ---------------------------------------------------------------------------
#define AS 68
#define VS 72
#define AT (64 * AS)
#define VT (64 * VS)
#define NT (Nv / 64)
#define ASMEM ((4 * AT + 2 * VT + 64 + 64 + 128 + 128) * 4)

__global__ __launch_bounds__(256, 2) void attn_tc(
    const float* __restrict__ Qr,
    const float* __restrict__ Kh, const float* __restrict__ Kl,
    const float* __restrict__ Vh, const float* __restrict__ Vl,
    float* __restrict__ Oh, float* __restrict__ Ol)
{
    extern __shared__ float sm[];
    float* Ksh    = sm;                // [64][68]
    float* Ksl    = Ksh + AT;
    float* Psh    = Ksl + AT;          // [64][68]  (Q staging at start)
    float* Psl    = Psh + AT;
    float* Vsh    = Psl + AT;          // [64][72]
    float* Vsl    = Vsh + VT;
    float* mstate = Vsl + VT;          // [64]
    float* lstate = mstate + 64;       // [64]
    float* pmax   = lstate + 64;       // [2][64]
    float* psum   = pmax + 128;        // [2][64]

    const int t    = threadIdx.x;
    const int lane = t & 31;
    const int warp = t >> 5;
    const int gid  = lane >> 2;
    const int tq   = lane & 3;
    const int wm   = warp >> 1;   // 0..3
    const int wn   = warp & 1;    // 0..1
    const int q0   = blockIdx.x * 64;
    const size_t base =
        (size_t)blockIdx.z * Nv * Dv + (size_t)blockIdx.y * DHv;

    const uint32_t sb = (uint32_t)__cvta_generic_to_shared(sm);
    const uint32_t sbKh = sb;
    const uint32_t sbKl = sb + AT * 4;
    const uint32_t sbVh = sb + 4 * AT * 4;
    const uint32_t sbVl = sb + (4 * AT + VT) * 4;

    // per-thread load slot for K/V tiles (1024 float4 chunks / 256 threads)
    // issue macros: 4 chunks per thread
#define ISSUE_K(kt)                                                            \
    {                                                                          \
        _Pragma("unroll")                                                      \
        for (int i = 0; i < 4; i++) {                                          \
            int idx = t + i * 256;                                             \
            int r   = idx >> 4;                                                \
            int c4  = (idx & 15) << 2;                                         \
            size_t g = base + (size_t)((kt) * 64 + r) * Dv + c4;               \
            cp_async16(sbKh + (r * AS + c4) * 4, Kh + g);                      \
            cp_async16(sbKl + (r * AS + c4) * 4, Kl + g);                      \
        }                                                                      \
        asm volatile("cp.async.commit_group;");                                \
    }
#define ISSUE_V(kt)                                                            \
    {                                                                          \
        _Pragma("unroll")                                                      \
        for (int i = 0; i < 4; i++) {                                          \
            int idx = t + i * 256;                                             \
            int r   = idx >> 4;                                                \
            int c4  = (idx & 15) << 2;                                         \
            size_t g = base + (size_t)((kt) * 64 + r) * Dv + c4;               \
            cp_async16(sbVh + (r * VS + c4) * 4, Vh + g);                      \
            cp_async16(sbVl + (r * VS + c4) * 4, Vl + g);                      \
        }                                                                      \
        asm volatile("cp.async.commit_group;");                                \
    }

    // prologue: start K(0), V(0) loads immediately
    ISSUE_K(0);
    ISSUE_V(0);

    // stage Q (raw) into Psh while loads fly, init state
#pragma unroll
    for (int i = 0; i < 4; i++) {
        int idx = t + i * 256;
        int r   = idx >> 4;
        int c4  = (idx & 15) << 2;
        float4 v = *(const float4*)&Qr[base + (size_t)(q0 + r) * Dv + c4];
        *(float4*)&Psh[r * AS + c4] = v;
    }
    if (t < 64) { mstate[t] = -1e30f; lstate[t] = 0.0f; }
    __syncthreads();

    // Q fragments -> split once into registers
    uint32_t qh[8][4], ql[8][4];
    {
        const int r = wm * 16 + gid;
#pragma unroll
        for (int ks = 0; ks < 8; ks++) {
            int c = ks * 8 + tq;
            tfsplit(Psh[r * AS + c],           qh[ks][0], ql[ks][0]);
            tfsplit(Psh[(r + 8) * AS + c],     qh[ks][1], ql[ks][1]);
            tfsplit(Psh[r * AS + c + 4],       qh[ks][2], ql[ks][2]);
            tfsplit(Psh[(r + 8) * AS + c + 4], qh[ks][3], ql[ks][3]);
        }
    }

    float o[4][4];
#pragma unroll
    for (int nf = 0; nf < 4; nf++)
#pragma unroll
        for (int c = 0; c < 4; c++) o[nf][c] = 0.0f;

    const int r_lo = wm * 16 + gid;
    const int r_hi = r_lo + 8;

    for (int kt = 0; kt < NT; kt++) {
        // K(kt) complete (V(kt) may still be in flight)
        asm volatile("cp.async.wait_group 1;" ::: "memory");
        __syncthreads();

        // S = Q K^T (split-tf32, all operands pre-split)
        float s[4][4];
#pragma unroll
        for (int nf = 0; nf < 4; nf++)
#pragma unroll
            for (int c = 0; c < 4; c++) s[nf][c] = 0.0f;
#pragma unroll
        for (int ks = 0; ks < 8; ks++) {
            const int c = ks * 8 + tq;
#pragma unroll
            for (int nf = 0; nf < 4; nf++) {
                int n = wn * 32 + nf * 8 + gid;
                uint32_t bh[2], bl[2];
                bh[0] = f2u(Ksh[n * AS + c]);
                bh[1] = f2u(Ksh[n * AS + c + 4]);
                bl[0] = f2u(Ksl[n * AS + c]);
                bl[1] = f2u(Ksl[n * AS + c + 4]);
                MMA3(s[nf], qh[ks], ql[ks], bh, bl);
            }
        }

        // phase A: per-row max
        float mx_lo = -1e30f, mx_hi = -1e30f;
#pragma unroll
        for (int nf = 0; nf < 4; nf++) {
            mx_lo = fmaxf(mx_lo, fmaxf(s[nf][0], s[nf][1]));
            mx_hi = fmaxf(mx_hi, fmaxf(s[nf][2], s[nf][3]));
        }
        mx_lo = fmaxf(mx_lo, __shfl_xor_sync(0xffffffffu, mx_lo, 1));
        mx_lo = fmaxf(mx_lo, __shfl_xor_sync(0xffffffffu, mx_lo, 2));
        mx_hi = fmaxf(mx_hi, __shfl_xor_sync(0xffffffffu, mx_hi, 1));
        mx_hi = fmaxf(mx_hi, __shfl_xor_sync(0xffffffffu, mx_hi, 2));
        if (tq == 0) {
            pmax[wn * 64 + r_lo] = mx_lo;
            pmax[wn * 64 + r_hi] = mx_hi;
        }
        __syncthreads();   // also: all warps done reading Ks

        // start K(kt+1) load now — overlaps softmax + PV
        if (kt + 1 < NT) ISSUE_K(kt + 1);

        // phase B: exp, sums, stage P split-once, rescale O
        float m_old_lo = mstate[r_lo], m_old_hi = mstate[r_hi];
        float nm_lo = fmaxf(m_old_lo, fmaxf(pmax[r_lo], pmax[64 + r_lo]));
        float nm_hi = fmaxf(m_old_hi, fmaxf(pmax[r_hi], pmax[64 + r_hi]));
        float sc_lo = __expf(m_old_lo - nm_lo);
        float sc_hi = __expf(m_old_hi - nm_hi);
        float sum_lo = 0.0f, sum_hi = 0.0f;
#pragma unroll
        for (int nf = 0; nf < 4; nf++) {
            float p0 = __expf(s[nf][0] - nm_lo);
            float p1 = __expf(s[nf][1] - nm_lo);
            float p2 = __expf(s[nf][2] - nm_hi);
            float p3 = __expf(s[nf][3] - nm_hi);
            sum_lo += p0 + p1;
            sum_hi += p2 + p3;
            int col = wn * 32 + nf * 8 + tq * 2;
            uint32_t h, l;
            tfsplit(p0, h, l);
            Psh[r_lo * AS + col] = u2f(h);     Psl[r_lo * AS + col] = u2f(l);
            tfsplit(p1, h, l);
            Psh[r_lo * AS + col + 1] = u2f(h); Psl[r_lo * AS + col + 1] = u2f(l);
            tfsplit(p2, h, l);
            Psh[r_hi * AS + col] = u2f(h);     Psl[r_hi * AS + col] = u2f(l);
            tfsplit(p3, h, l);
            Psh[r_hi * AS + col + 1] = u2f(h); Psl[r_hi * AS + col + 1] = u2f(l);
        }
        sum_lo += __shfl_xor_sync(0xffffffffu, sum_lo, 1);
        sum_lo += __shfl_xor_sync(0xffffffffu, sum_lo, 2);
        sum_hi += __shfl_xor_sync(0xffffffffu, sum_hi, 1);
        sum_hi += __shfl_xor_sync(0xffffffffu, sum_hi, 2);
        if (tq == 0) {
            psum[wn * 64 + r_lo] = sum_lo;
            psum[wn * 64 + r_hi] = sum_hi;
        }
#pragma unroll
        for (int nf = 0; nf < 4; nf++) {
            o[nf][0] *= sc_lo; o[nf][1] *= sc_lo;
            o[nf][2] *= sc_hi; o[nf][3] *= sc_hi;
        }

        // V(kt) complete. Outstanding after this: K(kt+1) (if any).
        if (kt + 1 < NT) {
            asm volatile("cp.async.wait_group 1;" ::: "memory");
        } else {
            asm volatile("cp.async.wait_group 0;" ::: "memory");
        }
        __syncthreads();   // P + psum + Vs visible to all

        if (wn == 0 && tq == 0) {
            lstate[r_lo] = lstate[r_lo] * sc_lo + psum[r_lo] + psum[64 + r_lo];
            lstate[r_hi] = lstate[r_hi] * sc_hi + psum[r_hi] + psum[64 + r_hi];
            mstate[r_lo] = nm_lo;
            mstate[r_hi] = nm_hi;
        }

        // O += P V (both pre-split)
#pragma unroll
        for (int ks = 0; ks < 8; ks++) {
            const int c = ks * 8 + tq;
            uint32_t ph[4], pl[4];
            ph[0] = f2u(Psh[r_lo * AS + c]);
            ph[1] = f2u(Psh[r_hi * AS + c]);
            ph[2] = f2u(Psh[r_lo * AS + c + 4]);
            ph[3] = f2u(Psh[r_hi * AS + c + 4]);
            pl[0] = f2u(Psl[r_lo * AS + c]);
            pl[1] = f2u(Psl[r_hi * AS + c]);
            pl[2] = f2u(Psl[r_lo * AS + c + 4]);
            pl[3] = f2u(Psl[r_hi * AS + c + 4]);
#pragma unroll
            for (int nf = 0; nf < 4; nf++) {
                int n = wn * 32 + nf * 8 + gid;
                uint32_t bh[2], bl[2];
                bh[0] = f2u(Vsh[(ks * 8 + tq) * VS + n]);
                bh[1] = f2u(Vsh[(ks * 8 + tq + 4) * VS + n]);
                bl[0] = f2u(Vsl[(ks * 8 + tq) * VS + n]);
                bl[1] = f2u(Vsl[(ks * 8 + tq + 4) * VS + n]);
                MMA3(o[nf], ph, pl, bh, bl);
            }
        }

        __syncthreads();   // all warps done reading Vs
        // start V(kt+1) load — overlaps next S + softmax
        if (kt + 1 < NT) ISSUE_V(kt + 1);
    }

    float inv_lo = 1.0f / lstate[r_lo];
    float inv_hi = 1.0f / lstate[r_hi];
#pragma unroll
    for (int nf = 0; nf < 4; nf++) {
        int col = wn * 32 + nf * 8 + tq * 2;
        uint32_t h0, l0, h1, l1;
        float v0 = o[nf][0] * inv_lo, v1 = o[nf][1] * inv_lo;
        tfsplit(v0, h0, l0); tfsplit(v1, h1, l1);
        size_t glo = base + (size_t)(q0 + r_lo) * Dv + col;
        *(float2*)&Oh[glo] = make_float2(u2f(h0), u2f(h1));
        *(float2*)&Ol[glo] = make_float2(u2f(l0), u2f(l1));
        float v2 = o[nf][2] * inv_hi, v3 = o[nf][3] * inv_hi;
        tfsplit(v2, h0, l0); tfsplit(v3, h1, l1);
        size_t ghi = base + (size_t)(q0 + r_hi) * Dv + col;
        *(float2*)&Oh[ghi] = make_float2(u2f(h0), u2f(h1));
        *(float2*)&Ol[ghi] = make_float2(u2f(l0), u2f(l1));
    }
}

// ---------------------------------------------------------------------------
extern "C" void kernel_launch(void* const* d_in, const int* in_sizes, int n_in,
                              void* d_out, int out_size)
{
    const float* q  = (const float*)d_in[0];
    const float* k  = (const float*)d_in[1];
    const float* v  = (const float*)d_in[2];
    const float* Wq = (const float*)d_in[3];
    const float* bq = (const float*)d_in[4];
    const float* Wk = (const float*)d_in[5];
    const float* bk = (const float*)d_in[6];
    const float* Wv = (const float*)d_in[7];
    const float* bv = (const float*)d_in[8];
    const float* Wo = (const float*)d_in[9];
    const float* bo = (const float*)d_in[10];
    float* out = (float*)d_out;

    float *xh, *xl, *wh, *wl, *qr, *kh, *kl, *vh, *vl, *ah, *al;
    cudaGetSymbolAddress((void**)&xh, g_Xh);
    cudaGetSymbolAddress((void**)&xl, g_Xl);
    cudaGetSymbolAddress((void**)&wh, g_WhA);
    cudaGetSymbolAddress((void**)&wl, g_WlA);
    cudaGetSymbolAddress((void**)&qr, g_Qr);
    cudaGetSymbolAddress((void**)&kh, g_Kh);
    cudaGetSymbolAddress((void**)&kl, g_Kl);
    cudaGetSymbolAddress((void**)&vh, g_Vh);
    cudaGetSymbolAddress((void**)&vl, g_Vl);
    cudaGetSymbolAddress((void**)&ah, g_Ah);
    cudaGetSymbolAddress((void**)&al, g_Al);

    cudaFuncSetAttribute(gemm_qkv,
                         cudaFuncAttributeMaxDynamicSharedMemorySize, GSMEM);
    cudaFuncSetAttribute(gemm_out,
                         cudaFuncAttributeMaxDynamicSharedMemorySize, GSMEM);
    cudaFuncSetAttribute(attn_tc,
                         cudaFuncAttributeMaxDynamicSharedMemorySize, ASMEM);

    split3_kernel<<<dim3(4096, 3), 256>>>(q, k, v, xh, xl);
    splitW_kernel<<<dim3(1024, 4), 256>>>(Wq, Wk, Wv, Wo, wh, wl);

    dim3 gg(Dv / 128, Mv / 128, 3);  // (8, 32, 3) fused QKV
    gemm_qkv<<<gg, 256, GSMEM>>>(xh, xl, wh, wl, bq, bk, bv,
                                 qr, kh, kl, vh, vl);

    attn_tc<<<dim3(Nv / 64, Hv, Bv), 256, ASMEM>>>(qr, kh, kl, vh, vl, ah, al);

    gemm_out<<<dim3(Dv / 128, Mv / 128), 256, GSMEM>>>(
        ah, al, wh + 3 * (size_t)Dv * Dv, wl + 3 * (size_t)Dv * Dv, bo, out);
}